// round 1
// baseline (speedup 1.0000x reference)
#include <cuda_runtime.h>
#include <cuda_bf16.h>
#include <cfloat>
#include <math.h>

// Problem constants
#define B_  64
#define C_  256
#define N_  20000
#define NT_ 64
#define K_  8
#define ROWS_ (B_ * K_ * NT_)   // 32768 output token rows

// Scratch (device globals; no allocation allowed)
__device__ float g_inv_snorm[N_];
__device__ float g_sims[B_ * N_];
__device__ int   g_top_idx[B_ * K_];

// ---------------------------------------------------------------------------
// Kernel 1: inverse L2 norm of each bank summary row (warp per row)
// ---------------------------------------------------------------------------
__global__ void snorm_kernel(const float* __restrict__ s) {
    int gw   = (blockIdx.x * blockDim.x + threadIdx.x) >> 5;
    int lane = threadIdx.x & 31;
    if (gw >= N_) return;
    const float* row = s + (size_t)gw * C_;
    float ss = 0.f;
#pragma unroll
    for (int i = 0; i < C_ / 32; i++) {
        float v = row[lane + 32 * i];
        ss += v * v;
    }
#pragma unroll
    for (int off = 16; off > 0; off >>= 1)
        ss += __shfl_xor_sync(0xffffffffu, ss, off);
    if (lane == 0) {
        float nrm = sqrtf(ss);
        g_inv_snorm[gw] = 1.0f / fmaxf(nrm, 1e-12f);
    }
}

// ---------------------------------------------------------------------------
// Kernel 2: sims[b][n] = (q[b] . s[n]) * inv_snorm[n]
// (skipping q normalization: positive per-row scale, ranking-invariant)
// 64x64 output tile per block, K chunked by 32.
// ---------------------------------------------------------------------------
__global__ void sims_kernel(const float* __restrict__ q,
                            const float* __restrict__ s) {
    __shared__ float Qs[64 * 33];
    __shared__ float Ss[64 * 33];
    int tid = threadIdx.x;
    int tx = tid & 15;       // 16 col groups
    int ty = tid >> 4;       // 16 row groups
    int n0 = blockIdx.x * 64;

    float acc[4][4];
#pragma unroll
    for (int i = 0; i < 4; i++)
#pragma unroll
        for (int j = 0; j < 4; j++) acc[i][j] = 0.f;

    for (int k0 = 0; k0 < C_; k0 += 32) {
        // load Q tile: 64 rows x 32 k
        for (int idx = tid; idx < 64 * 32; idx += 256) {
            int r = idx >> 5, kk = idx & 31;
            Qs[r * 33 + kk] = q[r * C_ + k0 + kk];
        }
        // load S tile: 64 rows x 32 k (zero pad beyond N)
        for (int idx = tid; idx < 64 * 32; idx += 256) {
            int r = idx >> 5, kk = idx & 31;
            int n = n0 + r;
            Ss[r * 33 + kk] = (n < N_) ? s[(size_t)n * C_ + k0 + kk] : 0.f;
        }
        __syncthreads();
#pragma unroll
        for (int kk = 0; kk < 32; kk++) {
            float a[4], bb[4];
#pragma unroll
            for (int i = 0; i < 4; i++) a[i] = Qs[(ty * 4 + i) * 33 + kk];
#pragma unroll
            for (int j = 0; j < 4; j++) bb[j] = Ss[(tx + 16 * j) * 33 + kk];
#pragma unroll
            for (int i = 0; i < 4; i++)
#pragma unroll
                for (int j = 0; j < 4; j++) acc[i][j] += a[i] * bb[j];
        }
        __syncthreads();
    }
#pragma unroll
    for (int i = 0; i < 4; i++) {
        int b = ty * 4 + i;
#pragma unroll
        for (int j = 0; j < 4; j++) {
            int n = n0 + tx + 16 * j;
            if (n < N_)
                g_sims[(size_t)b * N_ + n] = acc[i][j] * g_inv_snorm[n];
        }
    }
}

// ---------------------------------------------------------------------------
// Kernel 3: top-8 per row. Per-thread register top-8, block merge with
// 8 selection rounds (descending order, ties -> lower index).
// ---------------------------------------------------------------------------
__global__ void topk_kernel() {
    __shared__ float sv[2048];
    __shared__ int   si[2048];
    __shared__ float rv[256];
    __shared__ int   ri[256];
    __shared__ int   rs[256];

    int b = blockIdx.x;
    int tid = threadIdx.x;
    const float* row = g_sims + (size_t)b * N_;

    float tv[8];
    int   ti[8];
#pragma unroll
    for (int p = 0; p < 8; p++) { tv[p] = -FLT_MAX; ti[p] = 0x7fffffff; }

    for (int n = tid; n < N_; n += 256) {
        float v = row[n];
        if (v > tv[7]) {
            tv[7] = v; ti[7] = n;
#pragma unroll
            for (int p = 7; p >= 1; p--) {
                bool sw = (tv[p] > tv[p - 1]) ||
                          (tv[p] == tv[p - 1] && ti[p] < ti[p - 1]);
                if (sw) {
                    float fv = tv[p]; tv[p] = tv[p - 1]; tv[p - 1] = fv;
                    int   fi = ti[p]; ti[p] = ti[p - 1]; ti[p - 1] = fi;
                }
            }
        }
    }
#pragma unroll
    for (int p = 0; p < 8; p++) { sv[tid * 8 + p] = tv[p]; si[tid * 8 + p] = ti[p]; }
    __syncthreads();

    for (int round = 0; round < 8; round++) {
        float bv = -FLT_MAX; int bi = 0x7fffffff; int bslot = 0;
#pragma unroll
        for (int p = 0; p < 8; p++) {
            float v = sv[tid * 8 + p];
            int idx = si[tid * 8 + p];
            if (v > bv || (v == bv && idx < bi)) { bv = v; bi = idx; bslot = tid * 8 + p; }
        }
        rv[tid] = bv; ri[tid] = bi; rs[tid] = bslot;
        __syncthreads();
        for (int off = 128; off > 0; off >>= 1) {
            if (tid < off) {
                if (rv[tid + off] > rv[tid] ||
                    (rv[tid + off] == rv[tid] && ri[tid + off] < ri[tid])) {
                    rv[tid] = rv[tid + off];
                    ri[tid] = ri[tid + off];
                    rs[tid] = rs[tid + off];
                }
            }
            __syncthreads();
        }
        if (tid == 0) {
            g_top_idx[b * K_ + round] = ri[0];
            sv[rs[0]] = -FLT_MAX;   // remove winner
        }
        __syncthreads();
    }
}

// ---------------------------------------------------------------------------
// Kernel 4: gathered GEMM (h = x @ W^T + bias) fused with LayerNorm + gate.
// Block tile: 32 rows x 256 cols (full C -> LN fuses in-register).
// Threads: 256 = 8 warps; warp ty owns rows ty*4..ty*4+3; lane tx owns cols
// tx + 32*j (j=0..7). Each thread: 32 accumulators.
// ---------------------------------------------------------------------------
__global__ void gemm_ln_kernel(const float* __restrict__ templates,
                               const float* __restrict__ W,
                               const float* __restrict__ bias,
                               const float* __restrict__ gamma,
                               const float* __restrict__ beta,
                               const float* __restrict__ gate_logit,
                               float* __restrict__ out) {
    __shared__ float As[32 * 33];
    __shared__ float Ws[32 * 257];
    __shared__ long long srow[32];

    int tid = threadIdx.x;
    int tx = tid & 31, ty = tid >> 5;
    int rt = blockIdx.x;

    if (tid < 32) {
        int row = rt * 32 + tid;
        int b  = row >> 9;          // /512
        int t  = row & 511;
        int k  = t >> 6;            // /64
        int nt = t & 63;
        srow[tid] = ((long long)g_top_idx[b * K_ + k] * NT_ + nt) * (long long)C_;
    }
    __syncthreads();

    float acc[4][8];
#pragma unroll
    for (int i = 0; i < 4; i++)
#pragma unroll
        for (int j = 0; j < 8; j++) acc[i][j] = 0.f;

    for (int k0 = 0; k0 < C_; k0 += 32) {
        for (int idx = tid; idx < 32 * 32; idx += 256) {
            int r = idx >> 5, kk = idx & 31;
            As[r * 33 + kk] = templates[srow[r] + k0 + kk];
        }
        for (int idx = tid; idx < 256 * 32; idx += 256) {
            int c = idx >> 5, kk = idx & 31;
            Ws[kk * 257 + c] = W[c * C_ + k0 + kk];
        }
        __syncthreads();
#pragma unroll
        for (int kk = 0; kk < 32; kk++) {
            float a[4];
#pragma unroll
            for (int i = 0; i < 4; i++) a[i] = As[(ty * 4 + i) * 33 + kk];
            float bf[8];
#pragma unroll
            for (int j = 0; j < 8; j++) bf[j] = Ws[kk * 257 + tx + 32 * j];
#pragma unroll
            for (int i = 0; i < 4; i++)
#pragma unroll
                for (int j = 0; j < 8; j++) acc[i][j] += a[i] * bf[j];
        }
        __syncthreads();
    }

    // epilogue: bias, LayerNorm (warp-level over full row), gamma/beta, gate
    float gl = gate_logit[0];
    float gate = 1.0f / (1.0f + expf(-gl));

    float bv[8], gv[8], bev[8];
#pragma unroll
    for (int j = 0; j < 8; j++) {
        int c = tx + 32 * j;
        bv[j]  = bias[c];
        gv[j]  = gamma[c];
        bev[j] = beta[c];
    }

    int row0 = rt * 32 + ty * 4;
#pragma unroll
    for (int i = 0; i < 4; i++) {
        float s1 = 0.f, s2 = 0.f;
#pragma unroll
        for (int j = 0; j < 8; j++) {
            float h = acc[i][j] + bv[j];
            acc[i][j] = h;
            s1 += h;
            s2 += h * h;
        }
#pragma unroll
        for (int off = 16; off > 0; off >>= 1) {
            s1 += __shfl_xor_sync(0xffffffffu, s1, off);
            s2 += __shfl_xor_sync(0xffffffffu, s2, off);
        }
        float mean = s1 * (1.0f / C_);
        float var  = s2 * (1.0f / C_) - mean * mean;
        float inv  = rsqrtf(var + 1e-5f);
        float* orow = out + (size_t)(row0 + i) * C_;
#pragma unroll
        for (int j = 0; j < 8; j++) {
            int c = tx + 32 * j;
            orow[c] = ((acc[i][j] - mean) * inv * gv[j] + bev[j]) * gate;
        }
    }

    // second output: per-batch gate value
    if (rt == 0 && tid < B_)
        out[(size_t)ROWS_ * C_ + tid] = gate;
}

// ---------------------------------------------------------------------------
extern "C" void kernel_launch(void* const* d_in, const int* in_sizes, int n_in,
                              void* d_out, int out_size) {
    const float* query      = (const float*)d_in[0];
    const float* summaries  = (const float*)d_in[1];
    const float* templates  = (const float*)d_in[2];
    const float* w_proj     = (const float*)d_in[3];
    const float* b_proj     = (const float*)d_in[4];
    const float* ln_gamma   = (const float*)d_in[5];
    const float* ln_beta    = (const float*)d_in[6];
    const float* gate_logit = (const float*)d_in[7];
    float* out = (float*)d_out;

    snorm_kernel<<<(N_ * 32 + 255) / 256, 256>>>(summaries);
    sims_kernel<<<(N_ + 63) / 64, 256>>>(query, summaries);
    topk_kernel<<<B_, 256>>>();
    gemm_ln_kernel<<<ROWS_ / 32, 256>>>(templates, w_proj, b_proj,
                                        ln_gamma, ln_beta, gate_logit, out);
}

// round 2
// speedup vs baseline: 1.7649x; 1.7649x over previous
#include <cuda_runtime.h>
#include <cuda_bf16.h>
#include <cfloat>
#include <math.h>

// Problem constants
#define B_  64
#define C_  256
#define N_  20000
#define NT_ 64
#define K_  8
#define ROWS_ (B_ * K_ * NT_)   // 32768 output token rows

// Scratch (device globals; no allocation allowed)
__device__ float g_inv_snorm[N_];
__device__ float g_sims[B_ * N_];
__device__ int   g_top_idx[B_ * K_];

__device__ __forceinline__ unsigned f2tf32(float f) {
    unsigned u;
    asm("cvt.rna.tf32.f32 %0, %1;" : "=r"(u) : "f"(f));
    return u;
}

__device__ __forceinline__ void mma_tf32(float* d, const unsigned* a, const unsigned* b) {
    asm volatile(
        "mma.sync.aligned.m16n8k8.row.col.f32.tf32.tf32.f32 "
        "{%0,%1,%2,%3}, {%4,%5,%6,%7}, {%8,%9}, {%0,%1,%2,%3};"
        : "+f"(d[0]), "+f"(d[1]), "+f"(d[2]), "+f"(d[3])
        : "r"(a[0]), "r"(a[1]), "r"(a[2]), "r"(a[3]),
          "r"(b[0]), "r"(b[1]));
}

// ---------------------------------------------------------------------------
// Kernel 1: inverse L2 norm of each bank summary row (warp per row)
// ---------------------------------------------------------------------------
__global__ void snorm_kernel(const float* __restrict__ s) {
    int gw   = (blockIdx.x * blockDim.x + threadIdx.x) >> 5;
    int lane = threadIdx.x & 31;
    if (gw >= N_) return;
    const float4* row = (const float4*)(s + (size_t)gw * C_);
    float ss = 0.f;
#pragma unroll
    for (int i = 0; i < 2; i++) {
        float4 v = row[lane + 32 * i];
        ss += v.x * v.x + v.y * v.y + v.z * v.z + v.w * v.w;
    }
#pragma unroll
    for (int off = 16; off > 0; off >>= 1)
        ss += __shfl_xor_sync(0xffffffffu, ss, off);
    if (lane == 0) {
        float nrm = sqrtf(ss);
        g_inv_snorm[gw] = 1.0f / fmaxf(nrm, 1e-12f);
    }
}

// ---------------------------------------------------------------------------
// Kernel 2: sims[b][n] = (q[b] . s[n]) * inv_snorm[n]   (exact fp32)
// Block tile 64 (b) x 128 (n); 256 threads; 32 acc per thread.
// ---------------------------------------------------------------------------
__global__ void __launch_bounds__(256) sims_kernel(const float* __restrict__ q,
                                                   const float* __restrict__ s) {
    __shared__ float Qs[64 * 33];
    __shared__ float Ss[128 * 33];
    int tid = threadIdx.x;
    int tx = tid & 31;      // n within tile: tx + 32*j
    int wy = tid >> 5;      // warp -> 8 b-rows
    int n0 = blockIdx.x * 128;

    float acc[8][4];
#pragma unroll
    for (int i = 0; i < 8; i++)
#pragma unroll
        for (int j = 0; j < 4; j++) acc[i][j] = 0.f;

    for (int k0 = 0; k0 < C_; k0 += 32) {
#pragma unroll
        for (int i = 0; i < 8; i++) {   // Qs: 64x32
            int idx = tid + 256 * i;
            int r = idx >> 5, kk = idx & 31;
            Qs[r * 33 + kk] = q[r * C_ + k0 + kk];
        }
#pragma unroll
        for (int i = 0; i < 16; i++) {  // Ss: 128x32
            int idx = tid + 256 * i;
            int r = idx >> 5, kk = idx & 31;
            int n = n0 + r;
            Ss[r * 33 + kk] = (n < N_) ? s[(size_t)n * C_ + k0 + kk] : 0.f;
        }
        __syncthreads();
#pragma unroll
        for (int kk = 0; kk < 32; kk++) {
            float a[8], bb[4];
#pragma unroll
            for (int i = 0; i < 8; i++) a[i] = Qs[(wy * 8 + i) * 33 + kk];
#pragma unroll
            for (int j = 0; j < 4; j++) bb[j] = Ss[(tx + 32 * j) * 33 + kk];
#pragma unroll
            for (int i = 0; i < 8; i++)
#pragma unroll
                for (int j = 0; j < 4; j++) acc[i][j] += a[i] * bb[j];
        }
        __syncthreads();
    }
#pragma unroll
    for (int j = 0; j < 4; j++) {
        int n = n0 + tx + 32 * j;
        if (n < N_) {
            float inv = g_inv_snorm[n];
#pragma unroll
            for (int i = 0; i < 8; i++)
                g_sims[(size_t)(wy * 8 + i) * N_ + n] = acc[i][j] * inv;
        }
    }
}

// ---------------------------------------------------------------------------
// Kernel 3: top-8 per row (unchanged, exact).
// ---------------------------------------------------------------------------
__global__ void topk_kernel() {
    __shared__ float sv[2048];
    __shared__ int   si[2048];
    __shared__ float rv[256];
    __shared__ int   ri[256];
    __shared__ int   rs[256];

    int b = blockIdx.x;
    int tid = threadIdx.x;
    const float* row = g_sims + (size_t)b * N_;

    float tv[8];
    int   ti[8];
#pragma unroll
    for (int p = 0; p < 8; p++) { tv[p] = -FLT_MAX; ti[p] = 0x7fffffff; }

    for (int n = tid; n < N_; n += 256) {
        float v = row[n];
        if (v > tv[7]) {
            tv[7] = v; ti[7] = n;
#pragma unroll
            for (int p = 7; p >= 1; p--) {
                bool sw = (tv[p] > tv[p - 1]) ||
                          (tv[p] == tv[p - 1] && ti[p] < ti[p - 1]);
                if (sw) {
                    float fv = tv[p]; tv[p] = tv[p - 1]; tv[p - 1] = fv;
                    int   fi = ti[p]; ti[p] = ti[p - 1]; ti[p - 1] = fi;
                }
            }
        }
    }
#pragma unroll
    for (int p = 0; p < 8; p++) { sv[tid * 8 + p] = tv[p]; si[tid * 8 + p] = ti[p]; }
    __syncthreads();

    for (int round = 0; round < 8; round++) {
        float bv = -FLT_MAX; int bi = 0x7fffffff; int bslot = 0;
#pragma unroll
        for (int p = 0; p < 8; p++) {
            float v = sv[tid * 8 + p];
            int idx = si[tid * 8 + p];
            if (v > bv || (v == bv && idx < bi)) { bv = v; bi = idx; bslot = tid * 8 + p; }
        }
        rv[tid] = bv; ri[tid] = bi; rs[tid] = bslot;
        __syncthreads();
        for (int off = 128; off > 0; off >>= 1) {
            if (tid < off) {
                if (rv[tid + off] > rv[tid] ||
                    (rv[tid + off] == rv[tid] && ri[tid + off] < ri[tid])) {
                    rv[tid] = rv[tid + off];
                    ri[tid] = ri[tid + off];
                    rs[tid] = rs[tid + off];
                }
            }
            __syncthreads();
        }
        if (tid == 0) {
            g_top_idx[b * K_ + round] = ri[0];
            sv[rs[0]] = -FLT_MAX;   // remove winner
        }
        __syncthreads();
    }
}

// ---------------------------------------------------------------------------
// Kernel 4: gathered GEMM via tf32 mma.sync, fused bias + LayerNorm + gate.
// Block: 64 rows x 256 cols (full C), 256 threads = 8 warps.
// Warp w owns cols [w*32, w*32+32) for all 64 rows: 4 m-tiles x 4 n-tiles
// of m16n8k8. Smem stride 36 words -> bank = (4r+c)%32, bijective over the
// (lane>>2, lane&3) fragment pattern: conflict-free.
// ---------------------------------------------------------------------------
__global__ void __launch_bounds__(256, 2)
gemm_ln_tc(const float* __restrict__ templates,
           const float* __restrict__ W,
           const float* __restrict__ bias,
           const float* __restrict__ gamma,
           const float* __restrict__ beta,
           const float* __restrict__ gate_logit,
           float* __restrict__ out) {
    __shared__ unsigned As[64 * 36];    // rows x k chunk (tf32 bits)
    __shared__ unsigned Ws[256 * 36];   // cout x k chunk (tf32 bits)
    __shared__ int srow[64];

    int tid  = threadIdx.x;
    int lane = tid & 31;
    int w    = tid >> 5;
    int lr   = lane >> 2;   // 0..7
    int lc   = lane & 3;    // 0..3
    int rt   = blockIdx.x;

    if (tid < 64) {
        int row = rt * 64 + tid;
        int b = row >> 9;          // /512
        int t = row & 511;
        srow[tid] = g_top_idx[b * K_ + (t >> 6)] * NT_ + (t & 63);
    }
    __syncthreads();

    float acc[4][4][4];
#pragma unroll
    for (int mt = 0; mt < 4; mt++)
#pragma unroll
        for (int nt = 0; nt < 4; nt++)
#pragma unroll
            for (int r = 0; r < 4; r++) acc[mt][nt][r] = 0.f;

    for (int k0 = 0; k0 < C_; k0 += 32) {
        // stage A: 64x32 = 512 float4
#pragma unroll
        for (int i = 0; i < 2; i++) {
            int idx = tid + 256 * i;
            int r = idx >> 3, qv = idx & 7;
            float4 v = *(const float4*)(templates + (size_t)srow[r] * C_ + k0 + qv * 4);
            uint4 u = make_uint4(f2tf32(v.x), f2tf32(v.y), f2tf32(v.z), f2tf32(v.w));
            *(uint4*)(As + r * 36 + qv * 4) = u;
        }
        // stage W: 256x32 = 2048 float4
#pragma unroll
        for (int i = 0; i < 8; i++) {
            int idx = tid + 256 * i;
            int c = idx >> 3, qv = idx & 7;
            float4 v = *(const float4*)(W + (size_t)c * C_ + k0 + qv * 4);
            uint4 u = make_uint4(f2tf32(v.x), f2tf32(v.y), f2tf32(v.z), f2tf32(v.w));
            *(uint4*)(Ws + c * 36 + qv * 4) = u;
        }
        __syncthreads();
#pragma unroll
        for (int ks = 0; ks < 4; ks++) {
            int k = ks * 8;
            unsigned afr[4][4], bfr[4][2];
#pragma unroll
            for (int mt = 0; mt < 4; mt++) {
                int r = mt * 16 + lr;
                afr[mt][0] = As[r * 36 + k + lc];
                afr[mt][1] = As[(r + 8) * 36 + k + lc];
                afr[mt][2] = As[r * 36 + k + lc + 4];
                afr[mt][3] = As[(r + 8) * 36 + k + lc + 4];
            }
#pragma unroll
            for (int nt = 0; nt < 4; nt++) {
                int c = w * 32 + nt * 8 + lr;
                bfr[nt][0] = Ws[c * 36 + k + lc];
                bfr[nt][1] = Ws[c * 36 + k + lc + 4];
            }
#pragma unroll
            for (int mt = 0; mt < 4; mt++)
#pragma unroll
                for (int nt = 0; nt < 4; nt++)
                    mma_tf32(acc[mt][nt], afr[mt], bfr[nt]);
        }
        __syncthreads();
    }

    // ---------------- epilogue: bias + LayerNorm + gate ----------------
    float gate = 1.0f / (1.0f + expf(-gate_logit[0]));

    float bv0[4], bv1[4], gv0[4], gv1[4], be0[4], be1[4];
#pragma unroll
    for (int nt = 0; nt < 4; nt++) {
        int c = w * 32 + nt * 8 + 2 * lc;
        bv0[nt] = bias[c];  bv1[nt] = bias[c + 1];
        gv0[nt] = gamma[c]; gv1[nt] = gamma[c + 1];
        be0[nt] = beta[c];  be1[nt] = beta[c + 1];
    }

    // reuse As smem for reductions (all warps past last k-loop sync)
    float* sP1   = (float*)As;        // [64][8]
    float* sP2   = sP1 + 512;         // [64][8]
    float* smean = sP1 + 1024;        // [64]
    float* sinv  = sP1 + 1088;        // [64]

#pragma unroll
    for (int mt = 0; mt < 4; mt++) {
        float p1a = 0.f, p2a = 0.f, p1b = 0.f, p2b = 0.f;
#pragma unroll
        for (int nt = 0; nt < 4; nt++) {
            float h0 = acc[mt][nt][0] + bv0[nt];
            float h1 = acc[mt][nt][1] + bv1[nt];
            float h2 = acc[mt][nt][2] + bv0[nt];
            float h3 = acc[mt][nt][3] + bv1[nt];
            acc[mt][nt][0] = h0; acc[mt][nt][1] = h1;
            acc[mt][nt][2] = h2; acc[mt][nt][3] = h3;
            p1a += h0 + h1;           p2a += h0 * h0 + h1 * h1;
            p1b += h2 + h3;           p2b += h2 * h2 + h3 * h3;
        }
#pragma unroll
        for (int off = 1; off <= 2; off <<= 1) {
            p1a += __shfl_xor_sync(0xffffffffu, p1a, off);
            p2a += __shfl_xor_sync(0xffffffffu, p2a, off);
            p1b += __shfl_xor_sync(0xffffffffu, p1b, off);
            p2b += __shfl_xor_sync(0xffffffffu, p2b, off);
        }
        if (lc == 0) {
            int r = mt * 16 + lr;
            sP1[r * 8 + w] = p1a;       sP2[r * 8 + w] = p2a;
            sP1[(r + 8) * 8 + w] = p1b; sP2[(r + 8) * 8 + w] = p2b;
        }
    }
    __syncthreads();

    if (tid < 64) {
        float s1 = 0.f, s2 = 0.f;
#pragma unroll
        for (int j = 0; j < 8; j++) { s1 += sP1[tid * 8 + j]; s2 += sP2[tid * 8 + j]; }
        float mean = s1 * (1.0f / C_);
        float var  = s2 * (1.0f / C_) - mean * mean;
        smean[tid] = mean;
        sinv[tid]  = rsqrtf(var + 1e-5f);
    }
    __syncthreads();

    size_t base = (size_t)rt * 64 * C_;
#pragma unroll
    for (int mt = 0; mt < 4; mt++) {
        int r0 = mt * 16 + lr;
        float m0 = smean[r0],     i0 = sinv[r0];
        float m1 = smean[r0 + 8], i1 = sinv[r0 + 8];
#pragma unroll
        for (int nt = 0; nt < 4; nt++) {
            int c = w * 32 + nt * 8 + 2 * lc;
            float2 o0, o1;
            o0.x = ((acc[mt][nt][0] - m0) * i0 * gv0[nt] + be0[nt]) * gate;
            o0.y = ((acc[mt][nt][1] - m0) * i0 * gv1[nt] + be1[nt]) * gate;
            o1.x = ((acc[mt][nt][2] - m1) * i1 * gv0[nt] + be0[nt]) * gate;
            o1.y = ((acc[mt][nt][3] - m1) * i1 * gv1[nt] + be1[nt]) * gate;
            *(float2*)(out + base + (size_t)r0 * C_ + c)       = o0;
            *(float2*)(out + base + (size_t)(r0 + 8) * C_ + c) = o1;
        }
    }

    if (rt == 0 && tid < B_)
        out[(size_t)ROWS_ * C_ + tid] = gate;
}

// ---------------------------------------------------------------------------
extern "C" void kernel_launch(void* const* d_in, const int* in_sizes, int n_in,
                              void* d_out, int out_size) {
    const float* query      = (const float*)d_in[0];
    const float* summaries  = (const float*)d_in[1];
    const float* templates  = (const float*)d_in[2];
    const float* w_proj     = (const float*)d_in[3];
    const float* b_proj     = (const float*)d_in[4];
    const float* ln_gamma   = (const float*)d_in[5];
    const float* ln_beta    = (const float*)d_in[6];
    const float* gate_logit = (const float*)d_in[7];
    float* out = (float*)d_out;

    snorm_kernel<<<(N_ * 32 + 255) / 256, 256>>>(summaries);
    sims_kernel<<<(N_ + 127) / 128, 256>>>(query, summaries);
    topk_kernel<<<B_, 256>>>();
    gemm_ln_tc<<<ROWS_ / 64, 256>>>(templates, w_proj, b_proj,
                                    ln_gamma, ln_beta, gate_logit, out);
}